// round 16
// baseline (speedup 1.0000x reference)
#include <cuda_runtime.h>
#include <cuda_bf16.h>
#include <cstdint>

// ---------------- problem constants ----------------
#define BB 32
#define SS 2048
#define UU 512
#define VV 32000
#define G4 (4*UU)          // 2048 gate width

// ---------------- scratch (device globals; no allocs) ----------------
__device__ float g_gates[BB*G4];
__device__ float g_dg[BB*UU];
__device__ float g_scores[BB*SS];
__device__ float g_context[BB*UU];
__device__ float g_mid[BB*UU];
__device__ float g_logits[BB*VV];
__device__ float g_pgen[BB];

// ---------------- helpers ----------------
__device__ __forceinline__ uint32_t f2tf32(float x) {
    uint32_t u;
    asm("cvt.rna.tf32.f32 %0, %1;" : "=r"(u) : "f"(x));
    return u;
}
__device__ __forceinline__ float4 cvt4(float4 v) {
    return make_float4(__uint_as_float(f2tf32(v.x)), __uint_as_float(f2tf32(v.y)),
                       __uint_as_float(f2tf32(v.z)), __uint_as_float(f2tf32(v.w)));
}
__device__ __forceinline__ void mma_tf32(float c[4], const uint32_t a[4],
                                         uint32_t b0, uint32_t b1) {
    asm volatile(
        "mma.sync.aligned.m16n8k8.row.col.f32.tf32.tf32.f32 "
        "{%0,%1,%2,%3},{%4,%5,%6,%7},{%8,%9},{%0,%1,%2,%3};"
        : "+f"(c[0]), "+f"(c[1]), "+f"(c[2]), "+f"(c[3])
        : "r"(a[0]), "r"(a[1]), "r"(a[2]), "r"(a[3]), "r"(b0), "r"(b1));
}
// accurate-for-small-x fast tanh: (e^2x - 1)/(e^2x + 1)
__device__ __forceinline__ float fast_tanh(float x) {
    float e = __expf(2.f * x);
    return __fdividef(e - 1.f, e + 1.f);
}
// k-interleave: 8 cols (lo.x..lo.w = k0..3, hi.x..hi.w = k4..7) stored so that
// slot(2c)=k_c, slot(2c+1)=k_{c+4}  ->  thread's {tig, tig+4} pair is adjacent.
__device__ __forceinline__ void st_ilv(float* dst, float4 lo, float4 hi) {
    *(float4*)(dst)     = make_float4(lo.x, hi.x, lo.y, hi.y);
    *(float4*)(dst + 4) = make_float4(lo.z, hi.z, lo.w, hi.w);
}

// ---------------- init ----------------
__global__ void init_kernel(const float* __restrict__ w_g_b) {
    int i = blockIdx.x * 256 + threadIdx.x;
    if (i < BB*VV)  g_logits[i] = 0.f;
    if (i < BB*G4)  { g_gates[i] = 0.f; g_scores[i] = 0.f; }
    if (i < BB*UU)  { g_context[i] = 0.f; g_mid[i] = 0.f; g_dg[i] = w_g_b[i & (UU-1)]; }
}

// ---------------- generic M=32 GEMM (TF32 tensor cores) ----------------
__global__ __launch_bounds__(256) void gemm32_tc(
    const float* __restrict__ A, const float* __restrict__ W,
    float* __restrict__ out, int lda, int ldw, int N, int kPerBlock)
{
    __shared__ float As[32][36];
    __shared__ float Ws[128][36];
    const int n0 = blockIdx.x * 128;
    const int k0 = blockIdx.y * kPerBlock;
    const int t = threadIdx.x, wid = t >> 5, lane = t & 31;
    const int gid = lane >> 2, tig = lane & 3;
    const int rr = t >> 3, kq = (t & 7) * 4;

    float acc[2][2][4] = {};

    for (int kb = k0; kb < k0 + kPerBlock; kb += 32) {
        {
            float4 v = *(const float4*)&A[(size_t)rr*lda + kb + kq];
            *(float4*)&As[rr][kq] = cvt4(v);
        }
        #pragma unroll
        for (int p = 0; p < 4; p++) {
            int n = rr + p*32;
            float4 v = *(const float4*)&W[(size_t)(n0+n)*ldw + kb + kq];
            *(float4*)&Ws[n][kq] = cvt4(v);
        }
        __syncthreads();
        #pragma unroll
        for (int kk = 0; kk < 32; kk += 8) {
            uint32_t a[2][4];
            #pragma unroll
            for (int mt = 0; mt < 2; mt++) {
                int m = mt*16 + gid;
                a[mt][0] = __float_as_uint(As[m  ][kk+tig]);
                a[mt][1] = __float_as_uint(As[m+8][kk+tig]);
                a[mt][2] = __float_as_uint(As[m  ][kk+tig+4]);
                a[mt][3] = __float_as_uint(As[m+8][kk+tig+4]);
            }
            #pragma unroll
            for (int nt = 0; nt < 2; nt++) {
                int u = wid*16 + nt*8 + gid;
                uint32_t b0 = __float_as_uint(Ws[u][kk+tig]);
                uint32_t b1 = __float_as_uint(Ws[u][kk+tig+4]);
                #pragma unroll
                for (int mt = 0; mt < 2; mt++)
                    mma_tf32(acc[mt][nt], a[mt], b0, b1);
            }
        }
        __syncthreads();
    }
    #pragma unroll
    for (int mt = 0; mt < 2; mt++)
        #pragma unroll
        for (int nt = 0; nt < 2; nt++) {
            int n = n0 + wid*16 + nt*8 + 2*tig;
            int m = mt*16 + gid;
            atomicAdd(&out[(size_t)m*N + n],     acc[mt][nt][0]);
            atomicAdd(&out[(size_t)m*N + n + 1], acc[mt][nt][1]);
            atomicAdd(&out[(size_t)(m+8)*N + n],     acc[mt][nt][2]);
            atomicAdd(&out[(size_t)(m+8)*N + n + 1], acc[mt][nt][3]);
        }
}

// ---------------- LSTM cell ----------------
__global__ void lstm_kernel(const float* __restrict__ bih, const float* __restrict__ bhh,
                            const float* __restrict__ c0,
                            float* __restrict__ h_out, float* __restrict__ c_out)
{
    int t = blockIdx.x * 256 + threadIdx.x;
    int b = t >> 9, u = t & (UU-1);
    const float* gr = &g_gates[b*G4];
    float gi = gr[u]        + bih[u]        + bhh[u];
    float gf = gr[512+u]    + bih[512+u]    + bhh[512+u];
    float gg = gr[1024+u]   + bih[1024+u]   + bhh[1024+u];
    float go = gr[1536+u]   + bih[1536+u]   + bhh[1536+u];
    float si = 1.f / (1.f + expf(-gi));
    float sf = 1.f / (1.f + expf(-gf));
    float so = 1.f / (1.f + expf(-go));
    float cn = sf * c0[t] + si * tanhf(gg);
    c_out[t] = cn;
    h_out[t] = so * tanhf(cn);
}

// ---------------- attention scores v3: 128x256 tile, double-buffered, ----------
// ---------------- k-interleaved smem (fragment loads are LDS.64)      ----------
// scores[b,s] += sum_u V_w[u]*tanh(g_dg[b,u] + enc[b,s,:]@w_e[u,:])
#define AT_STAGE 13824   // floats per stage (4608 + 9216)
__global__ __launch_bounds__(512) void attn_scores_tc3(
    const float* __restrict__ enc, const float* __restrict__ w_e,
    const float* __restrict__ V_w)
{
    extern __shared__ float sm[];
    const int u0 = blockIdx.x * 256;     // u-half (grid.x = 2, fastest -> L2 pair)
    const int r0 = blockIdx.y * 128;     // row tile (one b per block)
    const int b  = r0 >> 11;
    const int t = threadIdx.x, wid = t >> 5, lane = t & 31;
    const int gid = lane >> 2, tig = lane & 3;
    const int warp_m = wid & 3;          // 4 groups of 32 rows
    const int warp_n = wid >> 2;         // 4 groups of 64 u
    const int rA = t >> 2, kA = (t & 3) * 8;     // As loader: 128r x 32k (one 8-group)
    const int rW = t >> 1, kW = (t & 1) * 16;    // Ws loader: 256u x 32k (two 8-groups)

    const float* encp = enc + (size_t)(r0 + rA)*UU + kA;
    const float* wep  = w_e + (size_t)(u0 + rW)*UU + kW;

    float acc[2][8][4] = {};
    float4 sA0, sA1, sW0, sW1, sW2, sW3;

    // prologue: stage 0 -> buf 0
    sA0 = *(const float4*)(encp);     sA1 = *(const float4*)(encp + 4);
    sW0 = *(const float4*)(wep);      sW1 = *(const float4*)(wep + 4);
    sW2 = *(const float4*)(wep + 8);  sW3 = *(const float4*)(wep + 12);
    {
        float* Ad = sm;  float* Wd = sm + 4608;
        st_ilv(&Ad[rA*36 + kA],     cvt4(sA0), cvt4(sA1));
        st_ilv(&Wd[rW*36 + kW],     cvt4(sW0), cvt4(sW1));
        st_ilv(&Wd[rW*36 + kW + 8], cvt4(sW2), cvt4(sW3));
    }
    __syncthreads();

    #pragma unroll 2
    for (int st = 0; st < 16; st++) {
        if (st < 15) {   // prefetch next stage into registers
            int kb = (st + 1) * 32;
            sA0 = *(const float4*)(encp + kb);     sA1 = *(const float4*)(encp + kb + 4);
            sW0 = *(const float4*)(wep + kb);      sW1 = *(const float4*)(wep + kb + 4);
            sW2 = *(const float4*)(wep + kb + 8);  sW3 = *(const float4*)(wep + kb + 12);
        }
        const float* As = sm + (st & 1) * AT_STAGE;
        const float* Ws = As + 4608;
        #pragma unroll
        for (int kk = 0; kk < 32; kk += 8) {
            // interleaved layout: cols {kk+tig, kk+tig+4} live at {kk+2tig, kk+2tig+1}
            uint32_t a[2][4];
            #pragma unroll
            for (int mt = 0; mt < 2; mt++) {
                int m = warp_m*32 + mt*16 + gid;
                float2 fa0 = *(const float2*)&As[(m  )*36 + kk + 2*tig];
                float2 fa1 = *(const float2*)&As[(m+8)*36 + kk + 2*tig];
                a[mt][0] = __float_as_uint(fa0.x);
                a[mt][1] = __float_as_uint(fa1.x);
                a[mt][2] = __float_as_uint(fa0.y);
                a[mt][3] = __float_as_uint(fa1.y);
            }
            #pragma unroll
            for (int nt = 0; nt < 8; nt++) {
                int u = warp_n*64 + nt*8 + gid;
                float2 fb = *(const float2*)&Ws[u*36 + kk + 2*tig];
                uint32_t b0 = __float_as_uint(fb.x);
                uint32_t b1 = __float_as_uint(fb.y);
                #pragma unroll
                for (int mt = 0; mt < 2; mt++)
                    mma_tf32(acc[mt][nt], a[mt], b0, b1);
            }
        }
        if (st < 15) {   // store prefetched stage into the other buffer
            float* Ad = sm + ((st + 1) & 1) * AT_STAGE;
            float* Wd = Ad + 4608;
            st_ilv(&Ad[rA*36 + kA],     cvt4(sA0), cvt4(sA1));
            st_ilv(&Wd[rW*36 + kW],     cvt4(sW0), cvt4(sW1));
            st_ilv(&Wd[rW*36 + kW + 8], cvt4(sW2), cvt4(sW3));
            __syncthreads();
        }
    }

    // epilogue: tanh + V_w reduce over this warp's 64 u, quad-shuffle, atomic
    float rowsum[2][2] = {};
    #pragma unroll
    for (int nt = 0; nt < 8; nt++) {
        int u = u0 + warp_n*64 + nt*8 + 2*tig;
        float vw0 = V_w[u],   dg0 = g_dg[b*UU + u];
        float vw1 = V_w[u+1], dg1 = g_dg[b*UU + u + 1];
        #pragma unroll
        for (int mt = 0; mt < 2; mt++) {
            rowsum[mt][0] += vw0*fast_tanh(dg0 + acc[mt][nt][0])
                           + vw1*fast_tanh(dg1 + acc[mt][nt][1]);
            rowsum[mt][1] += vw0*fast_tanh(dg0 + acc[mt][nt][2])
                           + vw1*fast_tanh(dg1 + acc[mt][nt][3]);
        }
    }
    #pragma unroll
    for (int mt = 0; mt < 2; mt++)
        #pragma unroll
        for (int h = 0; h < 2; h++) {
            float s = rowsum[mt][h];
            s += __shfl_xor_sync(0xffffffffu, s, 1);
            s += __shfl_xor_sync(0xffffffffu, s, 2);
            if (tig == 0) {
                int row = warp_m*32 + mt*16 + h*8 + gid;
                atomicAdd(&g_scores[r0 + row], s);
            }
        }
}

// ---------------- softmax over S per batch ----------------
__global__ void softmax_kernel(float* __restrict__ attn_out) {
    int b = blockIdx.x, t = threadIdx.x;
    __shared__ float red[256];
    const float* sc = &g_scores[b*SS];
    float mx = -1e30f;
    for (int s = t; s < SS; s += 256) mx = fmaxf(mx, sc[s]);
    red[t] = mx; __syncthreads();
    for (int o = 128; o > 0; o >>= 1) { if (t < o) red[t] = fmaxf(red[t], red[t+o]); __syncthreads(); }
    mx = red[0]; __syncthreads();
    float sum = 0.f;
    for (int s = t; s < SS; s += 256) sum += expf(sc[s] - mx);
    red[t] = sum; __syncthreads();
    for (int o = 128; o > 0; o >>= 1) { if (t < o) red[t] += red[t+o]; __syncthreads(); }
    float inv = 1.f / red[0];
    for (int s = t; s < SS; s += 256) attn_out[b*SS + s] = expf(sc[s] - mx) * inv;
}

// ---------------- context = attn @ enc ----------------
__global__ void context_kernel(const float* __restrict__ enc, const float* __restrict__ attn) {
    int b = blockIdx.x, uc = blockIdx.y, scb = blockIdx.z;
    int u = uc*128 + threadIdx.x;
    const float* ap = &attn[b*SS + scb*512];
    const float* ep = &enc[((size_t)b*SS + scb*512)*UU + u];
    float acc = 0.f;
    #pragma unroll 4
    for (int s = 0; s < 512; s++)
        acc += ap[s] * ep[(size_t)s*UU];
    atomicAdd(&g_context[b*UU + u], acc);
}

// ---------------- p_gen ----------------
__global__ void pgen_kernel(const float* __restrict__ x, const float* __restrict__ w_x_w,
                            const float* __restrict__ w_x_b,
                            const float* __restrict__ w_h, const float* __restrict__ w_s,
                            const float* __restrict__ h_o)
{
    int b = blockIdx.x, t = threadIdx.x;
    __shared__ float red[256];
    float s = 0.f;
    for (int v = t; v < VV; v += 256) s += x[(size_t)b*VV + v] * w_x_w[v];
    for (int u = t; u < UU; u += 256) s += g_context[b*UU + u]*w_h[u] + h_o[b*UU + u]*w_s[u];
    red[t] = s; __syncthreads();
    for (int o = 128; o > 0; o >>= 1) { if (t < o) red[t] += red[t+o]; __syncthreads(); }
    if (t == 0) g_pgen[b] = 1.f / (1.f + expf(-(red[0] + w_x_b[0])));
}

// ---------------- finalize ----------------
__global__ void finalize_kernel(const float* __restrict__ f_c_b,
                                float* __restrict__ logits_o, float* __restrict__ copy_o)
{
    int i = blockIdx.x * 256 + threadIdx.x;
    if (i < BB*VV) {
        int b = i / VV, v = i - b*VV;
        logits_o[i] = (g_logits[i] + f_c_b[v]) * g_pgen[b];
    } else if (i < BB*VV + BB*SS) {
        int j = i - BB*VV;
        int b = j >> 11;
        copy_o[j] = g_scores[j] * (1.f - g_pgen[b]);
    }
}

// ---------------- launch ----------------
extern "C" void kernel_launch(void* const* d_in, const int* in_sizes, int n_in,
                              void* d_out, int out_size)
{
    (void)in_sizes; (void)n_in; (void)out_size;
    const float* new_tokens = (const float*)d_in[0];
    const float* enc        = (const float*)d_in[1];
    const float* h0         = (const float*)d_in[2];
    const float* c0         = (const float*)d_in[3];
    const float* coverage   = (const float*)d_in[4];
    const float* W_ih       = (const float*)d_in[5];
    const float* W_hh       = (const float*)d_in[6];
    const float* b_ih       = (const float*)d_in[7];
    const float* b_hh       = (const float*)d_in[8];
    const float* w_d        = (const float*)d_in[9];
    const float* w_e        = (const float*)d_in[10];
    const float* w_g_w      = (const float*)d_in[11];
    const float* w_g_b      = (const float*)d_in[12];
    const float* V_w        = (const float*)d_in[13];
    const float* w_c        = (const float*)d_in[14];
    const float* f_c_w      = (const float*)d_in[15];
    const float* f_c_b      = (const float*)d_in[16];
    const float* w_h        = (const float*)d_in[17];
    const float* w_s        = (const float*)d_in[18];
    const float* w_x_w      = (const float*)d_in[19];
    const float* w_x_b      = (const float*)d_in[20];

    float* out      = (float*)d_out;
    float* logits_o = out;
    float* attn_o   = out + BB*VV;
    float* h_o      = attn_o + BB*SS;
    float* c_o      = h_o + BB*UU;
    float* copy_o   = c_o + BB*UU;

    float *p_gates, *p_dg, *p_mid, *p_logits, *p_context;
    cudaGetSymbolAddress((void**)&p_gates,   g_gates);
    cudaGetSymbolAddress((void**)&p_dg,      g_dg);
    cudaGetSymbolAddress((void**)&p_mid,     g_mid);
    cudaGetSymbolAddress((void**)&p_logits,  g_logits);
    cudaGetSymbolAddress((void**)&p_context, g_context);

    cudaFuncSetAttribute(attn_scores_tc3,
                         cudaFuncAttributeMaxDynamicSharedMemorySize,
                         2 * AT_STAGE * (int)sizeof(float));

    init_kernel<<<4000, 256>>>(w_g_b);
    // gates = x @ W_ih.T  (N=2048, K=32000, 25-way k-split)
    gemm32_tc<<<dim3(16, 25), 256>>>(new_tokens, W_ih, p_gates, 32000, 32000, G4, 1280);
    // gates += h @ W_hh.T
    gemm32_tc<<<dim3(16, 4), 256>>>(h0, W_hh, p_gates, 512, 512, G4, 128);
    lstm_kernel<<<64, 256>>>(b_ih, b_hh, c0, h_o, c_o);
    // g_dg = w_g_b + h_new @ w_d.T + coverage @ w_g_w.T
    gemm32_tc<<<dim3(4, 4), 256>>>(h_o, w_d, p_dg, 512, 512, UU, 128);
    gemm32_tc<<<dim3(4, 4), 256>>>(coverage, w_g_w, p_dg, 2048, 2048, UU, 512);
    // raw scores (fused enc@w_e.T -> tanh -> V_w reduce), TF32 MMA v3
    attn_scores_tc3<<<dim3(2, BB*SS/128), 512, 2*AT_STAGE*sizeof(float)>>>(enc, w_e, V_w);
    softmax_kernel<<<32, 256>>>(attn_o);
    context_kernel<<<dim3(32, 4, 4), 128>>>(enc, attn_o);
    // mid = [h_new, context] @ w_c.T
    gemm32_tc<<<dim3(4, 4), 256>>>(h_o, w_c, p_mid, 512, 1024, UU, 128);
    gemm32_tc<<<dim3(4, 4), 256>>>(p_context, w_c + 512, p_mid, 512, 1024, UU, 128);
    pgen_kernel<<<32, 256>>>(new_tokens, w_x_w, w_x_b, w_h, w_s, h_o);
    // logits_raw = mid @ f_c_w.T
    gemm32_tc<<<dim3(250, 1), 256>>>(p_mid, f_c_w, p_logits, 512, 512, VV, 512);
    finalize_kernel<<<(BB*VV + BB*SS + 255)/256, 256>>>(f_c_b, logits_o, copy_o);
}